// round 8
// baseline (speedup 1.0000x reference)
#include <cuda_runtime.h>
#include <cuda_bf16.h>
#include <cstdint>

#define VOCAB   50000
#define NCELLS  16384
#define NQUADS  4096                 // 4 cells/quad, warp-sized token block
#define GROUPS  4
#define BPG     74                   // blocks per group
#define GRID    (GROUPS * BPG)       // 296 = 2 per SM -> single wave
#define THREADS 512                  // 16 warps
#define SLICE   (VOCAB / GROUPS)     // 12500 floats
#define SLICE_BYTES (SLICE * 4)      // 50000 B smem
#define SLICE_PAIRS (SLICE / 2)      // 6250 row-pairs per slice
#define PPB     85                   // ceil(6250/74) row-pairs per block
#define MAXQ    4                    // quads per warp upper bound
#define ZCHUNK  56                   // out floats zeroed per block (296*56>=16384)

__device__ float    g_proj[VOCAB];
__device__ unsigned g_slice_ctr[GROUPS];   // +74 per replay each (monotonic)
__device__ unsigned g_zero_ctr;            // +296 per replay (monotonic)

__global__ void __launch_bounds__(THREADS, 2) fused_kernel(
    const int*   __restrict__ x,
    const float* __restrict__ E,
    const float* __restrict__ W,
    const float* __restrict__ bias,
    float*       __restrict__ out)
{
    extern __shared__ float s_slice[];    // 50 KB

    int tid  = threadIdx.x;
    int lane = tid & 31;
    int wid  = tid >> 5;                  // 0..15
    int b    = blockIdx.x;
    int grp  = b / BPG;                   // 0..3  (slice owned)
    int j    = b % BPG;                   // 0..73

    // ---- prolog: zero own out-chunk, prefetch x quads, read bias ----
    if (tid < ZCHUNK) {
        int o = b * ZCHUNK + tid;
        if (o < NCELLS) out[o] = 0.0f;
    }

    const int4* __restrict__ x4 = reinterpret_cast<const int4*>(x);
    int4 tq[MAXQ];
    #pragma unroll
    for (int i = 0; i < MAXQ; ++i) {
        int q = j + BPG * (wid + 16 * i);
        if (q < NQUADS) tq[i] = x4[q * 32 + lane];
    }
    float bv = (grp == 0) ? bias[0] : 0.0f;

    __syncthreads();                      // zero stores done block-wide

    unsigned ztarget = 0;
    if (tid == 0) {
        unsigned old;
        asm volatile("atom.add.release.gpu.u32 %0, [%1], %2;"
                     : "=r"(old) : "l"(&g_zero_ctr), "r"(1u) : "memory");
        ztarget = old - (old % (unsigned)GRID) + (unsigned)GRID;
    }

    // ================= Phase A: proj rows of own slice =================
    {
        const float4* __restrict__ e4 = reinterpret_cast<const float4*>(E);
        const float4* __restrict__ w4 = reinterpret_cast<const float4*>(W);
        float4 wa = w4[lane];
        float4 wb = w4[lane + 32];

        int pp_end = (j + 1) * PPB;
        if (pp_end > SLICE_PAIRS) pp_end = SLICE_PAIRS;

        for (int pp = j * PPB + wid; pp < pp_end; pp += 16) {
            int row0 = (grp * SLICE_PAIRS + pp) * 2;

            float4 a0 = e4[(size_t)row0 * 64 + lane];
            float4 a1 = e4[(size_t)row0 * 64 + lane + 32];
            float4 b0 = e4[(size_t)(row0 + 1) * 64 + lane];
            float4 b1 = e4[(size_t)(row0 + 1) * 64 + lane + 32];

            float s0 = 0.f, s1 = 0.f;
            s0 = fmaf(a0.x, wa.x, s0); s0 = fmaf(a0.y, wa.y, s0);
            s0 = fmaf(a0.z, wa.z, s0); s0 = fmaf(a0.w, wa.w, s0);
            s0 = fmaf(a1.x, wb.x, s0); s0 = fmaf(a1.y, wb.y, s0);
            s0 = fmaf(a1.z, wb.z, s0); s0 = fmaf(a1.w, wb.w, s0);
            s1 = fmaf(b0.x, wa.x, s1); s1 = fmaf(b0.y, wa.y, s1);
            s1 = fmaf(b0.z, wa.z, s1); s1 = fmaf(b0.w, wa.w, s1);
            s1 = fmaf(b1.x, wb.x, s1); s1 = fmaf(b1.y, wb.y, s1);
            s1 = fmaf(b1.z, wb.z, s1); s1 = fmaf(b1.w, wb.w, s1);

            #pragma unroll
            for (int o = 16; o > 0; o >>= 1) {
                s0 += __shfl_xor_sync(0xFFFFFFFFu, s0, o);
                s1 += __shfl_xor_sync(0xFFFFFFFFu, s1, o);
            }
            if (lane == 0) {
                g_proj[row0]     = s0;
                g_proj[row0 + 1] = s1;
            }
        }
    }

    // ============ slice rendezvous (single wave -> no deadlock) ============
    __syncthreads();                      // all g_proj stores of this block done
    if (tid == 0) {
        unsigned old;
        asm volatile("atom.add.release.gpu.u32 %0, [%1], %2;"
                     : "=r"(old) : "l"(&g_slice_ctr[grp]), "r"(1u) : "memory");
        unsigned starget = old - (old % (unsigned)BPG) + (unsigned)BPG;
        unsigned cur;
        do {
            asm volatile("ld.acquire.gpu.u32 %0, [%1];"
                         : "=r"(cur) : "l"(&g_slice_ctr[grp]) : "memory");
        } while (cur < starget);
        // also ensure every block finished zeroing out[] (long done by now)
        do {
            asm volatile("ld.acquire.gpu.u32 %0, [%1];"
                         : "=r"(cur) : "l"(&g_zero_ctr) : "memory");
        } while (cur < ztarget);
    }
    __syncthreads();

    // ============ Phase B: fill own 50 KB slice, gather, accumulate ============
    {
        const float4* __restrict__ gp4 =
            reinterpret_cast<const float4*>(g_proj + grp * SLICE);
        float4* s4 = reinterpret_cast<float4*>(s_slice);
        #pragma unroll 7
        for (int i = tid; i < SLICE / 4; i += THREADS)
            s4[i] = gp4[i];
    }
    __syncthreads();

    #pragma unroll
    for (int i = 0; i < MAXQ; ++i) {
        int q = j + BPG * (wid + 16 * i);
        if (q >= NQUADS) break;

        int4 t = tq[i];
        int base = grp * SLICE;
        float s = 0.0f;
        unsigned i0 = (unsigned)(t.x - base);
        unsigned i1 = (unsigned)(t.y - base);
        unsigned i2 = (unsigned)(t.z - base);
        unsigned i3 = (unsigned)(t.w - base);
        if (i0 < (unsigned)SLICE) s += s_slice[i0];
        if (i1 < (unsigned)SLICE) s += s_slice[i1];
        if (i2 < (unsigned)SLICE) s += s_slice[i2];
        if (i3 < (unsigned)SLICE) s += s_slice[i3];

        s += __shfl_xor_sync(0xFFFFFFFFu, s, 4);
        s += __shfl_xor_sync(0xFFFFFFFFu, s, 2);
        s += __shfl_xor_sync(0xFFFFFFFFu, s, 1);

        if ((lane & 7) == 0)
            atomicAdd(&out[q * 4 + (lane >> 3)], s + bv);
    }
}

extern "C" void kernel_launch(void* const* d_in, const int* in_sizes, int n_in,
                              void* d_out, int out_size)
{
    const int*   x = (const int*)  d_in[0];
    const float* E = (const float*)d_in[1];
    const float* W = (const float*)d_in[2];
    const float* b = (const float*)d_in[3];
    float* out = (float*)d_out;

    static bool attr_done = false;
    if (!attr_done) {
        cudaFuncSetAttribute(fused_kernel,
                             cudaFuncAttributeMaxDynamicSharedMemorySize,
                             SLICE_BYTES);
        attr_done = true;
    }

    fused_kernel<<<GRID, THREADS, SLICE_BYTES>>>(x, E, W, b, out);
}